// round 9
// baseline (speedup 1.0000x reference)
#include <cuda_runtime.h>
#include <cstdint>

#define K_DIM   2048
#define N_EXP   64
#define TM      128
#define TK      64
#define NKT     32
#define THREADS 512
#define ASTRIDE 72
#define ASTAGE  (TM * ASTRIDE)          // 9216 floats
#define BWORDS  4096                    // uint32 per B-frag stage (16KB)
#define WSTRIDE 68
#define WSTAGE  (N_EXP * WSTRIDE)       // 4352 floats (17KB)
#define LDL     72
#define TOPK_TEMP 2.0f
// A: 3*36864  B: 3*16384  W: 3*17408  = 212,  total bytes:
#define SMEM_BYTES (3*ASTAGE*4 + 3*BWORDS*4 + 3*WSTAGE*4)   // 212,  211968

__device__ uint32_t g_wfrag[NKT * BWORDS];

__device__ __forceinline__ uint32_t pack2(float f0, float f1) {
    uint32_t r;
    asm("cvt.rn.bf16x2.f32 %0, %1, %2;" : "=r"(r) : "f"(f1), "f"(f0));
    return r;
}
__device__ __forceinline__ void split2(float f0, float f1, uint32_t &h, uint32_t &l) {
    h = pack2(f0, f1);
    float h0 = __uint_as_float(h << 16);
    float h1 = __uint_as_float(h & 0xFFFF0000u);
    l = pack2(f0 - h0, f1 - h1);
}
__device__ __forceinline__ void mma16816(float *d,
                                         uint32_t a0, uint32_t a1, uint32_t a2, uint32_t a3,
                                         uint32_t b0, uint32_t b1) {
    asm volatile("mma.sync.aligned.m16n8k16.row.col.f32.bf16.bf16.f32 "
                 "{%0,%1,%2,%3}, {%4,%5,%6,%7}, {%8,%9}, {%0,%1,%2,%3};"
                 : "+f"(d[0]), "+f"(d[1]), "+f"(d[2]), "+f"(d[3])
                 : "r"(a0), "r"(a1), "r"(a2), "r"(a3), "r"(b0), "r"(b1));
}
__device__ __forceinline__ void cp16(uint32_t dst, const void* src) {
    asm volatile("cp.async.cg.shared.global [%0], [%1], 16;" :: "r"(dst), "l"(src));
}

__global__ __launch_bounds__(256)
void dhr_wprep_kernel(const float* __restrict__ w)
{
    const int kt = blockIdx.x;
    const int t  = threadIdx.x;
    const int bp  = t & 31;
    const int bks = bp >> 3;
    const int brg = (bp >> 2) & 1;
    const int bn0 = t >> 5;
    const int bln = (bn0 << 2) | (bp & 3);
    const float* pW = w + bn0 * K_DIM + kt * TK + 2 * bp;
    uint32_t* dst0 = g_wfrag + kt * BWORDS;
    #pragma unroll
    for (int i = 0; i < 8; i++) {
        float2 wv = *(const float2*)(pW + i * 8 * K_DIM);
        uint32_t h, l; split2(wv.x, wv.y, h, l);
        uint32_t* d = dst0 + (((bks * 8 + i) * 32 + bln) << 2);
        d[brg] = h; d[2 + brg] = l;
    }
}

__global__ __launch_bounds__(THREADS, 1)
void dhr_hybrid_kernel(const float* __restrict__ x,
                       const float* __restrict__ w,
                       const float* __restrict__ bias,
                       const int*   __restrict__ mat,
                       float* __restrict__ out)
{
    extern __shared__ __align__(16) float smem[];
    uint32_t* Bbase = (uint32_t*)(smem + 3 * ASTAGE);
    float*    Wbase = smem + 3 * ASTAGE + 3 * BWORDS;

    const int t    = threadIdx.x;
    const int wid  = t >> 5;
    const int lane = t & 31;
    const long rowBase = (long)blockIdx.x * TM;

    const uint32_t aSmem = (uint32_t)__cvta_generic_to_shared(smem);
    const uint32_t bSmem = (uint32_t)__cvta_generic_to_shared(Bbase);
    const uint32_t wSmem = (uint32_t)__cvta_generic_to_shared(Wbase);

    // tensor warps: wid<12 -> mt=wid>>1 (rows mt*16..+15 of 0..95), nH=wid&1
    // ffma warps:   wid>=12 -> rows 96..127, experts split
    const int  q  = lane & 3;
    const int  g  = lane >> 2;
    const int  mt = wid >> 1;
    const int  nH = wid & 1;
    const bool isTensor = (wid < 12);

    float acc[4][4];           // tensor: [j][frag]
    float4 facc[4][4];         // ffma: [row][expert] k-partials
    #pragma unroll
    for (int i = 0; i < 4; i++)
        #pragma unroll
        for (int j = 0; j < 4; j++) {
            acc[i][j] = 0.f;
            facc[i][j] = make_float4(0.f, 0.f, 0.f, 0.f);
        }

    // ffma thread mapping: 4 rows x 4 experts
    const int frow = 96 + (lane & 7) * 4;                        // 96..124
    const int fexp = ((wid - 12) * 4 + (lane >> 3)) * 4;         // 0..60

    // ---- prologue: stages 0,1 ----
    #pragma unroll
    for (int s0 = 0; s0 < 2; s0++) {
        #pragma unroll
        for (int ss = 0; ss < 4; ss++) {
            int idx = ss * THREADS + t;
            int r = idx >> 4, cc = idx & 15;
            cp16(aSmem + (s0 * ASTAGE + r * ASTRIDE) * 4 + cc * 16,
                 x + (rowBase + r) * K_DIM + s0 * TK + cc * 4);
        }
        #pragma unroll
        for (int ss = 0; ss < 2; ss++) {
            int idx = ss * THREADS + t;
            cp16(bSmem + s0 * BWORDS * 4 + idx * 16,
                 g_wfrag + s0 * BWORDS + idx * 4);
        }
        #pragma unroll
        for (int ss = 0; ss < 2; ss++) {
            int idx = ss * THREADS + t;       // 0..1023
            int e = idx >> 4, kc = idx & 15;
            cp16(wSmem + (s0 * WSTAGE + e * WSTRIDE) * 4 + kc * 16,
                 w + e * K_DIM + s0 * TK + kc * 4);
        }
        asm volatile("cp.async.commit_group;");
    }

    // ---- mainloop ----
    for (int kt = 0; kt < NKT; kt++) {
        asm volatile("cp.async.wait_group %0;" :: "n"(1));
        __syncthreads();

        if (kt + 2 < NKT) {
            int s = (kt + 2) % 3;
            #pragma unroll
            for (int ss = 0; ss < 4; ss++) {
                int idx = ss * THREADS + t;
                int r = idx >> 4, cc = idx & 15;
                cp16(aSmem + (s * ASTAGE + r * ASTRIDE) * 4 + cc * 16,
                     x + (rowBase + r) * K_DIM + (kt + 2) * TK + cc * 4);
            }
            #pragma unroll
            for (int ss = 0; ss < 2; ss++) {
                int idx = ss * THREADS + t;
                cp16(bSmem + s * BWORDS * 4 + idx * 16,
                     g_wfrag + (kt + 2) * BWORDS + idx * 4);
            }
            #pragma unroll
            for (int ss = 0; ss < 2; ss++) {
                int idx = ss * THREADS + t;
                int e = idx >> 4, kc = idx & 15;
                cp16(wSmem + (s * WSTAGE + e * WSTRIDE) * 4 + kc * 16,
                     w + e * K_DIM + (kt + 2) * TK + kc * 4);
            }
        }
        asm volatile("cp.async.commit_group;");

        const int st = kt % 3;

        if (isTensor) {
            const float*    As = smem + st * ASTAGE;
            const uint32_t* Bs = Bbase + st * BWORDS;
            #pragma unroll
            for (int ks = 0; ks < 4; ks++) {
                const float* p = As + (mt * 16 + g) * ASTRIDE + ks * 16 + 2 * q;
                float2 v0 = *(const float2*)(p);
                float2 v1 = *(const float2*)(p + 8 * ASTRIDE);
                float2 v2 = *(const float2*)(p + 8);
                float2 v3 = *(const float2*)(p + 8 * ASTRIDE + 8);
                uint32_t ah[4], al[4];
                split2(v0.x, v0.y, ah[0], al[0]);
                split2(v1.x, v1.y, ah[1], al[1]);
                split2(v2.x, v2.y, ah[2], al[2]);
                split2(v3.x, v3.y, ah[3], al[3]);
                #pragma unroll
                for (int j = 0; j < 4; j++) {
                    int tt = nH * 4 + j;
                    uint4 bf = *(const uint4*)(Bs + (((ks * 8 + tt) * 32 + lane) << 2));
                    mma16816(acc[j], ah[0], ah[1], ah[2], ah[3], bf.x, bf.y);
                    mma16816(acc[j], ah[0], ah[1], ah[2], ah[3], bf.z, bf.w);
                    mma16816(acc[j], al[0], al[1], al[2], al[3], bf.x, bf.y);
                }
            }
        } else {
            const float* As = smem + st * ASTAGE;
            const float* Ws = Wbase + st * WSTAGE;
            #pragma unroll
            for (int kk = 0; kk < 16; kk++) {
                float4 a4[4], b4[4];
                #pragma unroll
                for (int i = 0; i < 4; i++)
                    a4[i] = *(const float4*)(As + (frow + i) * ASTRIDE + kk * 4);
                #pragma unroll
                for (int j = 0; j < 4; j++)
                    b4[j] = *(const float4*)(Ws + (fexp + j) * WSTRIDE + kk * 4);
                #pragma unroll
                for (int i = 0; i < 4; i++)
                    #pragma unroll
                    for (int j = 0; j < 4; j++) {
                        facc[i][j].x = fmaf(a4[i].x, b4[j].x, facc[i][j].x);
                        facc[i][j].y = fmaf(a4[i].y, b4[j].y, facc[i][j].y);
                        facc[i][j].z = fmaf(a4[i].z, b4[j].z, facc[i][j].z);
                        facc[i][j].w = fmaf(a4[i].w, b4[j].w, facc[i][j].w);
                    }
            }
        }
    }
    __syncthreads();

    // ---- epilogue: logits + bias into SMEM ----
    float* L = smem;
    if (isTensor) {
        #pragma unroll
        for (int j = 0; j < 4; j++) {
            int c = nH * 32 + j * 8 + 2 * q;
            float b0 = __ldg(&bias[c]);
            float b1 = __ldg(&bias[c + 1]);
            int r0 = mt * 16 + g;
            L[r0 * LDL + c]           = acc[j][0] + b0;
            L[r0 * LDL + c + 1]       = acc[j][1] + b1;
            L[(r0 + 8) * LDL + c]     = acc[j][2] + b0;
            L[(r0 + 8) * LDL + c + 1] = acc[j][3] + b1;
        }
    } else {
        #pragma unroll
        for (int i = 0; i < 4; i++)
            #pragma unroll
            for (int j = 0; j < 4; j++) {
                float v = (facc[i][j].x + facc[i][j].y) + (facc[i][j].z + facc[i][j].w);
                L[(frow + i) * LDL + fexp + j] = v + __ldg(&bias[fexp + j]);
            }
    }
    __syncthreads();

    // ---- routing: one thread per row ----
    if (t < TM) {
        bool any_immature = false;
        #pragma unroll 8
        for (int e = 0; e < N_EXP; e++)
            any_immature |= (__ldg(&mat[e]) == 0);

        float* row = &L[t * LDL];
        if (!any_immature) {
            float v1 = -__int_as_float(0x7f800000), v2 = v1;
            int i1 = 0, i2 = 0;
            #pragma unroll 8
            for (int e = 0; e < N_EXP; e++) {
                float v = row[e];
                if (v > v1)      { v2 = v1; i2 = i1; v1 = v; i1 = e; }
                else if (v > v2) { v2 = v;  i2 = e; }
            }
            float e2  = __expf(v2 - v1);
            float inv = 1.0f / (1.0f + e2);
            #pragma unroll 8
            for (int e = 0; e < N_EXP; e++) row[e] = 0.0f;
            row[i1] = inv;
            row[i2] = e2 * inv;
        } else {
            float m = -__int_as_float(0x7f800000);
            #pragma unroll 8
            for (int e = 0; e < N_EXP; e++) m = fmaxf(m, row[e]);
            float s = 0.0f;
            float tmp[N_EXP];
            #pragma unroll 8
            for (int e = 0; e < N_EXP; e++) {
                float v = __expf((row[e] - m) * (1.0f / TOPK_TEMP));
                tmp[e] = v; s += v;
            }
            float invs = 1.0f / s;
            #pragma unroll 8
            for (int e = 0; e < N_EXP; e++) row[e] = tmp[e] * invs;
        }
    }
    __syncthreads();

    // ---- coalesced float4 store of 128x64 tile ----
    #pragma unroll
    for (int s = 0; s < (TM * N_EXP / 4) / THREADS; s++) {   // 4
        int idx = s * THREADS + t;
        int r = idx >> 4;
        int c = (idx & 15) << 2;
        float4 v = *(const float4*)&L[r * LDL + c];
        *(float4*)(out + (rowBase + r) * N_EXP + c) = v;
    }
}

extern "C" void kernel_launch(void* const* d_in, const int* in_sizes, int n_in,
                              void* d_out, int out_size)
{
    const float* x   = (const float*)d_in[0];   // [16384, 2048]
    const float* w   = (const float*)d_in[1];   // [64, 2048]
    const float* b   = (const float*)d_in[2];   // [64]
    const int*   mat = (const int*)  d_in[3];   // [64]
    float* out = (float*)d_out;                 // [16384, 64]

    cudaFuncSetAttribute(dhr_hybrid_kernel,
                         cudaFuncAttributeMaxDynamicSharedMemorySize, SMEM_BYTES);

    dhr_wprep_kernel<<<NKT, 256>>>(w);

    int rows = in_sizes[0] / K_DIM;             // 16384
    int grid = rows / TM;                       // 128
    dhr_hybrid_kernel<<<grid, THREADS, SMEM_BYTES>>>(x, w, b, mat, out);
}

// round 10
// speedup vs baseline: 1.7992x; 1.7992x over previous
#include <cuda_runtime.h>
#include <cstdint>

#define K_DIM   2048
#define N_EXP   64
#define TM      128
#define TK      64
#define NKT     32
#define THREADS 512
#define ASTRIDE 76                      // bank-perfect for FFMA row loads
#define ASTAGE  (TM * ASTRIDE)          // 9728 floats (38912 B)
#define BWORDS  4096                    // uint32 per B-frag stage (16KB)
#define WSTRIDE 68
#define WSTAGE  (N_EXP * WSTRIDE)       // 4352 floats (17408 B)
#define LDL     72
#define TOPK_TEMP 2.0f
#define SMEM_BYTES (3*ASTAGE*4 + 3*BWORDS*4 + 3*WSTAGE*4)   // 218112

__device__ uint32_t g_wfrag[NKT * BWORDS];

__device__ __forceinline__ uint32_t pack2(float f0, float f1) {
    uint32_t r;
    asm("cvt.rn.bf16x2.f32 %0, %1, %2;" : "=r"(r) : "f"(f1), "f"(f0));
    return r;
}
__device__ __forceinline__ void split2(float f0, float f1, uint32_t &h, uint32_t &l) {
    h = pack2(f0, f1);
    float h0 = __uint_as_float(h << 16);
    float h1 = __uint_as_float(h & 0xFFFF0000u);
    l = pack2(f0 - h0, f1 - h1);
}
__device__ __forceinline__ void mma16816(float *d,
                                         uint32_t a0, uint32_t a1, uint32_t a2, uint32_t a3,
                                         uint32_t b0, uint32_t b1) {
    asm volatile("mma.sync.aligned.m16n8k16.row.col.f32.bf16.bf16.f32 "
                 "{%0,%1,%2,%3}, {%4,%5,%6,%7}, {%8,%9}, {%0,%1,%2,%3};"
                 : "+f"(d[0]), "+f"(d[1]), "+f"(d[2]), "+f"(d[3])
                 : "r"(a0), "r"(a1), "r"(a2), "r"(a3), "r"(b0), "r"(b1));
}
__device__ __forceinline__ void cp16(uint32_t dst, const void* src) {
    asm volatile("cp.async.cg.shared.global [%0], [%1], 16;" :: "r"(dst), "l"(src));
}

__global__ __launch_bounds__(256)
void dhr_wprep_kernel(const float* __restrict__ w)
{
    const int kt = blockIdx.x;
    const int t  = threadIdx.x;
    const int bp  = t & 31;
    const int bks = bp >> 3;
    const int brg = (bp >> 2) & 1;
    const int bn0 = t >> 5;
    const int bln = (bn0 << 2) | (bp & 3);
    const float* pW = w + bn0 * K_DIM + kt * TK + 2 * bp;
    uint32_t* dst0 = g_wfrag + kt * BWORDS;
    #pragma unroll
    for (int i = 0; i < 8; i++) {
        float2 wv = *(const float2*)(pW + i * 8 * K_DIM);
        uint32_t h, l; split2(wv.x, wv.y, h, l);
        uint32_t* d = dst0 + (((bks * 8 + i) * 32 + bln) << 2);
        d[brg] = h; d[2 + brg] = l;
    }
}

__global__ __launch_bounds__(THREADS, 1)
void dhr_hybrid2_kernel(const float* __restrict__ x,
                        const float* __restrict__ w,
                        const float* __restrict__ bias,
                        const int*   __restrict__ mat,
                        float* __restrict__ out)
{
    extern __shared__ __align__(16) float smem[];
    uint32_t* Bbase = (uint32_t*)(smem + 3 * ASTAGE);
    float*    Wbase = smem + 3 * ASTAGE + 3 * BWORDS;

    const int t    = threadIdx.x;
    const int wid  = t >> 5;
    const int lane = t & 31;
    const long rowBase = (long)blockIdx.x * TM;

    const uint32_t aSmem = (uint32_t)__cvta_generic_to_shared(smem);
    const uint32_t bSmem = (uint32_t)__cvta_generic_to_shared(Bbase);
    const uint32_t wSmem = (uint32_t)__cvta_generic_to_shared(Wbase);

    const int  q  = lane & 3;
    const int  g  = lane >> 2;
    const int  mt = wid >> 1;          // tensor: rows mt*16..+15 (mt<6)
    const int  nH = wid & 1;
    const bool isTensor = (wid < 12);

    // FFMA mapping: warp f handles experts f*16..+15; rows 96..127
    const int fw     = wid - 12;                    // 0..3
    const int row_g  = lane & 7;                    // rows 96+row_g+8i
    const int e_base = fw * 16 + (lane >> 3) * 4;   // 4 experts

    float  acc[4][4];          // tensor accumulators
    float4 facc[4][4];         // ffma k-partials [row i][expert j]
    #pragma unroll
    for (int i = 0; i < 4; i++)
        #pragma unroll
        for (int j = 0; j < 4; j++) {
            acc[i][j] = 0.f;
            facc[i][j] = make_float4(0.f, 0.f, 0.f, 0.f);
        }

    // ---- prologue: stages 0,1 ----
    #pragma unroll
    for (int s0 = 0; s0 < 2; s0++) {
        #pragma unroll
        for (int ss = 0; ss < 4; ss++) {
            int idx = ss * THREADS + t;
            int r = idx >> 4, cc = idx & 15;
            cp16(aSmem + (s0 * ASTAGE + r * ASTRIDE) * 4 + cc * 16,
                 x + (rowBase + r) * K_DIM + s0 * TK + cc * 4);
        }
        #pragma unroll
        for (int ss = 0; ss < 2; ss++) {
            int idx = ss * THREADS + t;
            cp16(bSmem + s0 * BWORDS * 4 + idx * 16,
                 g_wfrag + s0 * BWORDS + idx * 4);
        }
        #pragma unroll
        for (int ss = 0; ss < 2; ss++) {
            int idx = ss * THREADS + t;
            int e = idx >> 4, kc = idx & 15;
            cp16(wSmem + (s0 * WSTAGE + e * WSTRIDE) * 4 + kc * 16,
                 w + e * K_DIM + s0 * TK + kc * 4);
        }
        asm volatile("cp.async.commit_group;");
    }

    // ---- mainloop ----
    for (int kt = 0; kt < NKT; kt++) {
        asm volatile("cp.async.wait_group %0;" :: "n"(1));
        __syncthreads();

        if (kt + 2 < NKT) {
            int s = (kt + 2) % 3;
            #pragma unroll
            for (int ss = 0; ss < 4; ss++) {
                int idx = ss * THREADS + t;
                int r = idx >> 4, cc = idx & 15;
                cp16(aSmem + (s * ASTAGE + r * ASTRIDE) * 4 + cc * 16,
                     x + (rowBase + r) * K_DIM + (kt + 2) * TK + cc * 4);
            }
            #pragma unroll
            for (int ss = 0; ss < 2; ss++) {
                int idx = ss * THREADS + t;
                cp16(bSmem + s * BWORDS * 4 + idx * 16,
                     g_wfrag + (kt + 2) * BWORDS + idx * 4);
            }
            #pragma unroll
            for (int ss = 0; ss < 2; ss++) {
                int idx = ss * THREADS + t;
                int e = idx >> 4, kc = idx & 15;
                cp16(wSmem + (s * WSTAGE + e * WSTRIDE) * 4 + kc * 16,
                     w + e * K_DIM + (kt + 2) * TK + kc * 4);
            }
        }
        asm volatile("cp.async.commit_group;");

        const int st = kt % 3;

        if (isTensor) {
            const float*    As = smem + st * ASTAGE;
            const uint32_t* Bs = Bbase + st * BWORDS;
            #pragma unroll
            for (int ks = 0; ks < 4; ks++) {
                const float* p = As + (mt * 16 + g) * ASTRIDE + ks * 16 + 2 * q;
                float2 v0 = *(const float2*)(p);
                float2 v1 = *(const float2*)(p + 8 * ASTRIDE);
                float2 v2 = *(const float2*)(p + 8);
                float2 v3 = *(const float2*)(p + 8 * ASTRIDE + 8);
                uint32_t ah[4], al[4];
                split2(v0.x, v0.y, ah[0], al[0]);
                split2(v1.x, v1.y, ah[1], al[1]);
                split2(v2.x, v2.y, ah[2], al[2]);
                split2(v3.x, v3.y, ah[3], al[3]);
                #pragma unroll
                for (int j = 0; j < 4; j++) {
                    int tt = nH * 4 + j;
                    uint4 bf = *(const uint4*)(Bs + (((ks * 8 + tt) * 32 + lane) << 2));
                    mma16816(acc[j], ah[0], ah[1], ah[2], ah[3], bf.x, bf.y);
                    mma16816(acc[j], ah[0], ah[1], ah[2], ah[3], bf.z, bf.w);
                    mma16816(acc[j], al[0], al[1], al[2], al[3], bf.x, bf.y);
                }
            }
        } else {
            const float* As = smem + st * ASTAGE + (96 + row_g) * ASTRIDE;
            const float* Ws = Wbase + st * WSTAGE + e_base * WSTRIDE;
            #pragma unroll
            for (int kk = 0; kk < 16; kk++) {
                float4 a4[4], b4[4];
                #pragma unroll
                for (int i = 0; i < 4; i++)
                    a4[i] = *(const float4*)(As + (8 * i) * ASTRIDE + kk * 4);
                #pragma unroll
                for (int j = 0; j < 4; j++)
                    b4[j] = *(const float4*)(Ws + j * WSTRIDE + kk * 4);
                #pragma unroll
                for (int i = 0; i < 4; i++)
                    #pragma unroll
                    for (int j = 0; j < 4; j++) {
                        facc[i][j].x = fmaf(a4[i].x, b4[j].x, facc[i][j].x);
                        facc[i][j].y = fmaf(a4[i].y, b4[j].y, facc[i][j].y);
                        facc[i][j].z = fmaf(a4[i].z, b4[j].z, facc[i][j].z);
                        facc[i][j].w = fmaf(a4[i].w, b4[j].w, facc[i][j].w);
                    }
            }
        }
    }
    __syncthreads();

    // ---- epilogue: logits + bias into SMEM ----
    float* L = smem;
    if (isTensor) {
        #pragma unroll
        for (int j = 0; j < 4; j++) {
            int c = nH * 32 + j * 8 + 2 * q;
            float b0 = __ldg(&bias[c]);
            float b1 = __ldg(&bias[c + 1]);
            int r0 = mt * 16 + g;
            L[r0 * LDL + c]           = acc[j][0] + b0;
            L[r0 * LDL + c + 1]       = acc[j][1] + b1;
            L[(r0 + 8) * LDL + c]     = acc[j][2] + b0;
            L[(r0 + 8) * LDL + c + 1] = acc[j][3] + b1;
        }
    } else {
        #pragma unroll
        for (int i = 0; i < 4; i++)
            #pragma unroll
            for (int j = 0; j < 4; j++) {
                float v = (facc[i][j].x + facc[i][j].y) + (facc[i][j].z + facc[i][j].w);
                L[(96 + row_g + 8 * i) * LDL + e_base + j] = v + __ldg(&bias[e_base + j]);
            }
    }
    __syncthreads();

    // ---- routing: one thread per row ----
    if (t < TM) {
        bool any_immature = false;
        #pragma unroll 8
        for (int e = 0; e < N_EXP; e++)
            any_immature |= (__ldg(&mat[e]) == 0);

        float* row = &L[t * LDL];
        if (!any_immature) {
            float v1 = -__int_as_float(0x7f800000), v2 = v1;
            int i1 = 0, i2 = 0;
            #pragma unroll 8
            for (int e = 0; e < N_EXP; e++) {
                float v = row[e];
                if (v > v1)      { v2 = v1; i2 = i1; v1 = v; i1 = e; }
                else if (v > v2) { v2 = v;  i2 = e; }
            }
            float e2  = __expf(v2 - v1);
            float inv = 1.0f / (1.0f + e2);
            #pragma unroll 8
            for (int e = 0; e < N_EXP; e++) row[e] = 0.0f;
            row[i1] = inv;
            row[i2] = e2 * inv;
        } else {
            float m = -__int_as_float(0x7f800000);
            #pragma unroll 8
            for (int e = 0; e < N_EXP; e++) m = fmaxf(m, row[e]);
            float s = 0.0f;
            float tmp[N_EXP];
            #pragma unroll 8
            for (int e = 0; e < N_EXP; e++) {
                float v = __expf((row[e] - m) * (1.0f / TOPK_TEMP));
                tmp[e] = v; s += v;
            }
            float invs = 1.0f / s;
            #pragma unroll 8
            for (int e = 0; e < N_EXP; e++) row[e] = tmp[e] * invs;
        }
    }
    __syncthreads();

    // ---- coalesced float4 store of 128x64 tile ----
    #pragma unroll
    for (int s = 0; s < (TM * N_EXP / 4) / THREADS; s++) {   // 4
        int idx = s * THREADS + t;
        int r = idx >> 4;
        int c = (idx & 15) << 2;
        float4 v = *(const float4*)&L[r * LDL + c];
        *(float4*)(out + (rowBase + r) * N_EXP + c) = v;
    }
}

extern "C" void kernel_launch(void* const* d_in, const int* in_sizes, int n_in,
                              void* d_out, int out_size)
{
    const float* x   = (const float*)d_in[0];   // [16384, 2048]
    const float* w   = (const float*)d_in[1];   // [64, 2048]
    const float* b   = (const float*)d_in[2];   // [64]
    const int*   mat = (const int*)  d_in[3];   // [64]
    float* out = (float*)d_out;                 // [16384, 64]

    cudaFuncSetAttribute(dhr_hybrid2_kernel,
                         cudaFuncAttributeMaxDynamicSharedMemorySize, SMEM_BYTES);

    dhr_wprep_kernel<<<NKT, 256>>>(w);

    int rows = in_sizes[0] / K_DIM;             // 16384
    int grid = rows / TM;                       // 128
    dhr_hybrid2_kernel<<<grid, THREADS, SMEM_BYTES>>>(x, w, b, mat, out);
}

// round 11
// speedup vs baseline: 3.3775x; 1.8772x over previous
#include <cuda_runtime.h>
#include <cstdint>

#define K_DIM   2048
#define N_EXP   64
#define TM      128
#define TK      64
#define NKT     32
#define UNITS   (128 * NKT)            // 4096 work units (row-tile, k-tile)
#define THREADS 512
#define ASTRIDE 72
#define ASTAGE  (TM * ASTRIDE)
#define BWORDS  4096
#define LDL     72
#define TOPK_TEMP 2.0f
#define SMEM_BYTES (3 * ASTAGE * 4 + 3 * BWORDS * 4)   // 159744

__device__ uint32_t g_wfrag[NKT * BWORDS];
__device__ float    g_part[128][3][TM * N_EXP];   // partial logits per tile/slot
__device__ unsigned g_cnt[128];                   // never reset; mod-count protocol

__device__ __forceinline__ uint32_t pack2(float f0, float f1) {
    uint32_t r;
    asm("cvt.rn.bf16x2.f32 %0, %1, %2;" : "=r"(r) : "f"(f1), "f"(f0));
    return r;
}
__device__ __forceinline__ void split2(float f0, float f1, uint32_t &h, uint32_t &l) {
    h = pack2(f0, f1);
    float h0 = __uint_as_float(h << 16);
    float h1 = __uint_as_float(h & 0xFFFF0000u);
    l = pack2(f0 - h0, f1 - h1);
}
__device__ __forceinline__ void mma16816(float *d,
                                         uint32_t a0, uint32_t a1, uint32_t a2, uint32_t a3,
                                         uint32_t b0, uint32_t b1) {
    asm volatile("mma.sync.aligned.m16n8k16.row.col.f32.bf16.bf16.f32 "
                 "{%0,%1,%2,%3}, {%4,%5,%6,%7}, {%8,%9}, {%0,%1,%2,%3};"
                 : "+f"(d[0]), "+f"(d[1]), "+f"(d[2]), "+f"(d[3])
                 : "r"(a0), "r"(a1), "r"(a2), "r"(a3), "r"(b0), "r"(b1));
}
__device__ __forceinline__ void cp16(uint32_t dst, const void* src) {
    asm volatile("cp.async.cg.shared.global [%0], [%1], 16;" :: "r"(dst), "l"(src));
}

__global__ __launch_bounds__(256)
void dhr_wprep_kernel(const float* __restrict__ w)
{
    const int kt = blockIdx.x;
    const int t  = threadIdx.x;
    const int bp  = t & 31;
    const int bks = bp >> 3;
    const int brg = (bp >> 2) & 1;
    const int bn0 = t >> 5;
    const int bln = (bn0 << 2) | (bp & 3);
    const float* pW = w + bn0 * K_DIM + kt * TK + 2 * bp;
    uint32_t* dst0 = g_wfrag + kt * BWORDS;
    #pragma unroll
    for (int i = 0; i < 8; i++) {
        float2 wv = *(const float2*)(pW + i * 8 * K_DIM);
        uint32_t h, l; split2(wv.x, wv.y, h, l);
        uint32_t* d = dst0 + (((bks * 8 + i) * 32 + bln) << 2);
        d[brg] = h; d[2 + brg] = l;
    }
}

__global__ __launch_bounds__(THREADS, 1)
void dhr_splitk_kernel(const float* __restrict__ x,
                       const float* __restrict__ bias,
                       const int*   __restrict__ mat,
                       float* __restrict__ out)
{
    extern __shared__ __align__(16) float smem[];
    uint32_t* Bbase = (uint32_t*)(smem + 3 * ASTAGE);
    __shared__ int sFlag;

    const int t    = threadIdx.x;
    const int wid  = t >> 5;
    const int lane = t & 31;
    const int q    = lane & 3;
    const int g    = lane >> 2;
    const int kh     = wid & 1;
    const int stripe = (wid >> 1) & 3;
    const int nH     = wid >> 3;
    const int mrow   = stripe * 32;

    const uint32_t aSmem = (uint32_t)__cvta_generic_to_shared(smem);
    const uint32_t bSmem = (uint32_t)__cvta_generic_to_shared(Bbase);

    const int NC   = gridDim.x;
    const int cIdx = blockIdx.x;
    const int uLo = (cIdx * UNITS + NC - 1) / NC;
    const int uHi = ((cIdx + 1) * UNITS + NC - 1) / NC;
    const int Ta = uLo >> 5, Tb = (uHi - 1) >> 5;

    for (int T = Ta; T <= Tb; T++) {
        const int kF = (T == Ta) ? (uLo - (T << 5)) : 0;
        const int kE = (T == Tb) ? (uHi - (T << 5)) : NKT;
        const int nk = kE - kF;
        const long rowBase = (long)T * TM;

        float acc[2][4][4];
        #pragma unroll
        for (int m = 0; m < 2; m++)
            #pragma unroll
            for (int j = 0; j < 4; j++)
                acc[m][j][0] = acc[m][j][1] = acc[m][j][2] = acc[m][j][3] = 0.f;

        // ---- prologue: stages 0,1 ----
        #pragma unroll
        for (int s0 = 0; s0 < 2; s0++) {
            if (s0 < nk) {
                #pragma unroll
                for (int ss = 0; ss < 4; ss++) {
                    int idx = ss * THREADS + t;
                    int r = idx >> 4, cc = idx & 15;
                    cp16(aSmem + (s0 * ASTAGE + r * ASTRIDE) * 4 + cc * 16,
                         x + (rowBase + r) * K_DIM + (kF + s0) * TK + cc * 4);
                }
                #pragma unroll
                for (int ss = 0; ss < 2; ss++) {
                    int idx = ss * THREADS + t;
                    cp16(bSmem + s0 * BWORDS * 4 + idx * 16,
                         g_wfrag + (kF + s0) * BWORDS + idx * 4);
                }
            }
            asm volatile("cp.async.commit_group;");
        }

        // ---- pipelined mainloop over this segment's k-tiles ----
        for (int i = 0; i < nk; i++) {
            asm volatile("cp.async.wait_group %0;" :: "n"(1));
            __syncthreads();

            if (i + 2 < nk) {
                int s = (i + 2) % 3;
                #pragma unroll
                for (int ss = 0; ss < 4; ss++) {
                    int idx = ss * THREADS + t;
                    int r = idx >> 4, cc = idx & 15;
                    cp16(aSmem + (s * ASTAGE + r * ASTRIDE) * 4 + cc * 16,
                         x + (rowBase + r) * K_DIM + (kF + i + 2) * TK + cc * 4);
                }
                #pragma unroll
                for (int ss = 0; ss < 2; ss++) {
                    int idx = ss * THREADS + t;
                    cp16(bSmem + s * BWORDS * 4 + idx * 16,
                         g_wfrag + (kF + i + 2) * BWORDS + idx * 4);
                }
            }
            asm volatile("cp.async.commit_group;");

            const float*    As = smem + (i % 3) * ASTAGE;
            const uint32_t* Bs = Bbase + (i % 3) * BWORDS;

            #pragma unroll
            for (int kk = 0; kk < 2; kk++) {
                const int ks = kh * 2 + kk;
                const float* p = As + (mrow + g) * ASTRIDE + ks * 16 + 2 * q;
                uint32_t ah[2][4], al[2][4];
                #pragma unroll
                for (int m = 0; m < 2; m++) {
                    const float* pm = p + m * 16 * ASTRIDE;
                    float2 v0 = *(const float2*)(pm);
                    float2 v1 = *(const float2*)(pm + 8 * ASTRIDE);
                    float2 v2 = *(const float2*)(pm + 8);
                    float2 v3 = *(const float2*)(pm + 8 * ASTRIDE + 8);
                    split2(v0.x, v0.y, ah[m][0], al[m][0]);
                    split2(v1.x, v1.y, ah[m][1], al[m][1]);
                    split2(v2.x, v2.y, ah[m][2], al[m][2]);
                    split2(v3.x, v3.y, ah[m][3], al[m][3]);
                }
                #pragma unroll
                for (int j = 0; j < 4; j++) {
                    int tt = nH * 4 + j;
                    uint4 bf = *(const uint4*)(Bs + (((ks * 8 + tt) * 32 + lane) << 2));
                    #pragma unroll
                    for (int m = 0; m < 2; m++) {
                        mma16816(acc[m][j], ah[m][0], ah[m][1], ah[m][2], ah[m][3], bf.x, bf.y);
                        mma16816(acc[m][j], ah[m][0], ah[m][1], ah[m][2], ah[m][3], bf.z, bf.w);
                        mma16816(acc[m][j], al[m][0], al[m][1], al[m][2], al[m][3], bf.x, bf.y);
                    }
                }
            }
        }
        asm volatile("cp.async.wait_group %0;" :: "n"(0));
        __syncthreads();

        // ---- flush partial logits (no bias) into SMEM, combine kh halves ----
        float* L = smem;
        if (kh == 0) {
            #pragma unroll
            for (int m = 0; m < 2; m++)
                #pragma unroll
                for (int j = 0; j < 4; j++) {
                    int c = (nH * 4 + j) * 8 + 2 * q;
                    int r0 = mrow + g + 16 * m;
                    L[r0 * LDL + c]           = acc[m][j][0];
                    L[r0 * LDL + c + 1]       = acc[m][j][1];
                    L[(r0 + 8) * LDL + c]     = acc[m][j][2];
                    L[(r0 + 8) * LDL + c + 1] = acc[m][j][3];
                }
        }
        __syncthreads();
        if (kh == 1) {
            #pragma unroll
            for (int m = 0; m < 2; m++)
                #pragma unroll
                for (int j = 0; j < 4; j++) {
                    int c = (nH * 4 + j) * 8 + 2 * q;
                    int r0 = mrow + g + 16 * m;
                    L[r0 * LDL + c]           += acc[m][j][0];
                    L[r0 * LDL + c + 1]       += acc[m][j][1];
                    L[(r0 + 8) * LDL + c]     += acc[m][j][2];
                    L[(r0 + 8) * LDL + c + 1] += acc[m][j][3];
                }
        }
        __syncthreads();

        // ---- store partial to gmem scratch ----
        const int cHead = ((T << 5) * NC) / UNITS;
        const int cLast = (((T << 5) + 31) * NC) / UNITS;
        const int slot  = cIdx - cHead;
        const int cnt   = cLast - cHead + 1;
        float* dst = &g_part[T][slot][0];
        #pragma unroll
        for (int s = 0; s < 4; s++) {
            int chunk = s * THREADS + t;        // 0..2047 float4s
            int r = chunk >> 4, c4 = chunk & 15;
            *(float4*)&dst[r * N_EXP + c4 * 4] = *(const float4*)&L[r * LDL + c4 * 4];
        }
        __threadfence();
        __syncthreads();
        if (t == 0) {
            unsigned old = atomicAdd(&g_cnt[T], 1u);
            sFlag = (((old + 1u) % (unsigned)cnt) == 0u) ? 1 : 0;
        }
        __syncthreads();

        if (sFlag) {
            __threadfence();
            // combine slots in fixed order + bias -> L
            #pragma unroll
            for (int s = 0; s < 4; s++) {
                int chunk = s * THREADS + t;
                int r = chunk >> 4, c4 = chunk & 15;
                float4 v = *(const float4*)&g_part[T][0][r * N_EXP + c4 * 4];
                for (int sl = 1; sl < cnt; sl++) {
                    float4 u = *(const float4*)&g_part[T][sl][r * N_EXP + c4 * 4];
                    v.x += u.x; v.y += u.y; v.z += u.z; v.w += u.w;
                }
                float4 bb = *(const float4*)&bias[c4 * 4];
                v.x += bb.x; v.y += bb.y; v.z += bb.z; v.w += bb.w;
                *(float4*)&L[r * LDL + c4 * 4] = v;
            }
            __syncthreads();

            // routing: one thread per row
            if (t < TM) {
                bool any_immature = false;
                #pragma unroll 8
                for (int e = 0; e < N_EXP; e++)
                    any_immature |= (__ldg(&mat[e]) == 0);

                float* row = &L[t * LDL];
                if (!any_immature) {
                    float v1 = -__int_as_float(0x7f800000), v2 = v1;
                    int i1 = 0, i2 = 0;
                    #pragma unroll 8
                    for (int e = 0; e < N_EXP; e++) {
                        float v = row[e];
                        if (v > v1)      { v2 = v1; i2 = i1; v1 = v; i1 = e; }
                        else if (v > v2) { v2 = v;  i2 = e; }
                    }
                    float e2  = __expf(v2 - v1);
                    float inv = 1.0f / (1.0f + e2);
                    #pragma unroll 8
                    for (int e = 0; e < N_EXP; e++) row[e] = 0.0f;
                    row[i1] = inv;
                    row[i2] = e2 * inv;
                } else {
                    float m = -__int_as_float(0x7f800000);
                    #pragma unroll 8
                    for (int e = 0; e < N_EXP; e++) m = fmaxf(m, row[e]);
                    float s = 0.0f;
                    float tmp[N_EXP];
                    #pragma unroll 8
                    for (int e = 0; e < N_EXP; e++) {
                        float v = __expf((row[e] - m) * (1.0f / TOPK_TEMP));
                        tmp[e] = v; s += v;
                    }
                    float invs = 1.0f / s;
                    #pragma unroll 8
                    for (int e = 0; e < N_EXP; e++) row[e] = tmp[e] * invs;
                }
            }
            __syncthreads();

            // coalesced float4 store of this tile
            #pragma unroll
            for (int s = 0; s < 4; s++) {
                int idx = s * THREADS + t;
                int r = idx >> 4;
                int c = (idx & 15) << 2;
                float4 v = *(const float4*)&L[r * LDL + c];
                *(float4*)(out + (rowBase + r) * N_EXP + c) = v;
            }
        }
        __syncthreads();   // L / stage0 region free before next segment's cp.async
    }
}

extern "C" void kernel_launch(void* const* d_in, const int* in_sizes, int n_in,
                              void* d_out, int out_size)
{
    const float* x   = (const float*)d_in[0];   // [16384, 2048]
    const float* w   = (const float*)d_in[1];   // [64, 2048]
    const float* b   = (const float*)d_in[2];   // [64]
    const int*   mat = (const int*)  d_in[3];   // [64]
    float* out = (float*)d_out;                 // [16384, 64]

    int nsm = 148;
    cudaDeviceGetAttribute(&nsm, cudaDevAttrMultiProcessorCount, 0);
    if (nsm < 1)   nsm = 148;
    if (nsm > 156) nsm = 156;   // keep per-tile partial count <= 3

    cudaFuncSetAttribute(dhr_splitk_kernel,
                         cudaFuncAttributeMaxDynamicSharedMemorySize, SMEM_BYTES);

    dhr_wprep_kernel<<<NKT, 256>>>(w);
    dhr_splitk_kernel<<<nsm, THREADS, SMEM_BYTES>>>(x, b, mat, out);
}

// round 12
// speedup vs baseline: 4.0929x; 1.2118x over previous
#include <cuda_runtime.h>
#include <cstdint>

#define K_DIM   2048
#define N_EXP   64
#define TK      64
#define NKT     32
#define THREADS 512
#define ASTRIDE 72
#define BWORDS  4096
#define LDL     72
#define TOPK_TEMP 2.0f

__device__ uint32_t g_wfrag[NKT * BWORDS];

__device__ __forceinline__ uint32_t pack2(float f0, float f1) {
    uint32_t r;
    asm("cvt.rn.bf16x2.f32 %0, %1, %2;" : "=r"(r) : "f"(f1), "f"(f0));
    return r;
}
__device__ __forceinline__ void split2(float f0, float f1, uint32_t &h, uint32_t &l) {
    h = pack2(f0, f1);
    float h0 = __uint_as_float(h << 16);
    float h1 = __uint_as_float(h & 0xFFFF0000u);
    l = pack2(f0 - h0, f1 - h1);
}
__device__ __forceinline__ void mma16816(float *d,
                                         uint32_t a0, uint32_t a1, uint32_t a2, uint32_t a3,
                                         uint32_t b0, uint32_t b1) {
    asm volatile("mma.sync.aligned.m16n8k16.row.col.f32.bf16.bf16.f32 "
                 "{%0,%1,%2,%3}, {%4,%5,%6,%7}, {%8,%9}, {%0,%1,%2,%3};"
                 : "+f"(d[0]), "+f"(d[1]), "+f"(d[2]), "+f"(d[3])
                 : "r"(a0), "r"(a1), "r"(a2), "r"(a3), "r"(b0), "r"(b1));
}
__device__ __forceinline__ void cp16(uint32_t dst, const void* src) {
    asm volatile("cp.async.cg.shared.global [%0], [%1], 16;" :: "r"(dst), "l"(src));
}

__global__ __launch_bounds__(256)
void dhr_wprep_kernel(const float* __restrict__ w)
{
    const int kt = blockIdx.x;
    const int t  = threadIdx.x;
    const int bp  = t & 31;
    const int bks = bp >> 3;
    const int brg = (bp >> 2) & 1;
    const int bn0 = t >> 5;
    const int bln = (bn0 << 2) | (bp & 3);
    const float* pW = w + bn0 * K_DIM + kt * TK + 2 * bp;
    uint32_t* dst0 = g_wfrag + kt * BWORDS;
    #pragma unroll
    for (int i = 0; i < 8; i++) {
        float2 wv = *(const float2*)(pW + i * 8 * K_DIM);
        uint32_t h, l; split2(wv.x, wv.y, h, l);
        uint32_t* d = dst0 + (((bks * 8 + i) * 32 + bln) << 2);
        d[brg] = h; d[2 + brg] = l;
    }
}

template<int MT>
__device__ __forceinline__ void run_tile(long rowBase,
                                         const float* __restrict__ x,
                                         const float* __restrict__ bias,
                                         const int*   __restrict__ mat,
                                         float* __restrict__ out,
                                         float* smem)
{
    constexpr int TMloc = MT * 16;
    constexpr int ASTG  = TMloc * ASTRIDE;      // floats per A stage
    constexpr int ACH   = MT * 256;             // float4 chunks per A stage
    constexpr int NCH   = (ACH + THREADS - 1) / THREADS;
    uint32_t* Bbase = (uint32_t*)(smem + 3 * ASTG);

    const int t    = threadIdx.x;
    const int wid  = t >> 5;
    const int lane = t & 31;
    const int q    = lane & 3;
    const int g    = lane >> 2;
    const int kh   = wid & 1;
    const int nH   = (wid >> 1) & 1;
    const int ws   = wid >> 2;                  // 0..3
    const int nMt  = (ws + 4 < MT) ? 2 : 1;     // m-tiles {ws, ws+4}

    const uint32_t aSmem = (uint32_t)__cvta_generic_to_shared(smem);
    const uint32_t bSmem = (uint32_t)__cvta_generic_to_shared(Bbase);

    float acc[2][4][4];
    #pragma unroll
    for (int m = 0; m < 2; m++)
        #pragma unroll
        for (int j = 0; j < 4; j++)
            acc[m][j][0] = acc[m][j][1] = acc[m][j][2] = acc[m][j][3] = 0.f;

    // ---- prologue: stages 0,1 ----
    #pragma unroll
    for (int s0 = 0; s0 < 2; s0++) {
        #pragma unroll
        for (int ss = 0; ss < NCH; ss++) {
            int idx = ss * THREADS + t;
            if (idx < ACH) {
                int r = idx >> 4, cc = idx & 15;
                cp16(aSmem + (s0 * ASTG + r * ASTRIDE) * 4 + cc * 16,
                     x + (rowBase + r) * K_DIM + s0 * TK + cc * 4);
            }
        }
        #pragma unroll
        for (int ss = 0; ss < 2; ss++) {
            int idx = ss * THREADS + t;
            cp16(bSmem + s0 * BWORDS * 4 + idx * 16,
                 g_wfrag + s0 * BWORDS + idx * 4);
        }
        asm volatile("cp.async.commit_group;");
    }

    // ---- mainloop (compile-time bounds) ----
    for (int kt = 0; kt < NKT; kt++) {
        asm volatile("cp.async.wait_group %0;" :: "n"(1));
        __syncthreads();

        if (kt + 2 < NKT) {
            int s = (kt + 2) % 3;
            #pragma unroll
            for (int ss = 0; ss < NCH; ss++) {
                int idx = ss * THREADS + t;
                if (idx < ACH) {
                    int r = idx >> 4, cc = idx & 15;
                    cp16(aSmem + (s * ASTG + r * ASTRIDE) * 4 + cc * 16,
                         x + (rowBase + r) * K_DIM + (kt + 2) * TK + cc * 4);
                }
            }
            #pragma unroll
            for (int ss = 0; ss < 2; ss++) {
                int idx = ss * THREADS + t;
                cp16(bSmem + s * BWORDS * 4 + idx * 16,
                     g_wfrag + (kt + 2) * BWORDS + idx * 4);
            }
        }
        asm volatile("cp.async.commit_group;");

        const float*    As = smem + (kt % 3) * ASTG;
        const uint32_t* Bs = Bbase + (kt % 3) * BWORDS;

        #pragma unroll
        for (int kk = 0; kk < 2; kk++) {
            const int ks = kh * 2 + kk;
            uint32_t ah[2][4], al[2][4];
            #pragma unroll
            for (int m = 0; m < 2; m++) {
                if (m < nMt) {
                    int mt = ws + 4 * m;
                    const float* pm = As + (mt * 16 + g) * ASTRIDE + ks * 16 + 2 * q;
                    float2 v0 = *(const float2*)(pm);
                    float2 v1 = *(const float2*)(pm + 8 * ASTRIDE);
                    float2 v2 = *(const float2*)(pm + 8);
                    float2 v3 = *(const float2*)(pm + 8 * ASTRIDE + 8);
                    split2(v0.x, v0.y, ah[m][0], al[m][0]);
                    split2(v1.x, v1.y, ah[m][1], al[m][1]);
                    split2(v2.x, v2.y, ah[m][2], al[m][2]);
                    split2(v3.x, v3.y, ah[m][3], al[m][3]);
                }
            }
            #pragma unroll
            for (int j = 0; j < 4; j++) {
                int tt = nH * 4 + j;
                uint4 bf = *(const uint4*)(Bs + (((ks * 8 + tt) * 32 + lane) << 2));
                #pragma unroll
                for (int m = 0; m < 2; m++) {
                    if (m < nMt) {
                        mma16816(acc[m][j], ah[m][0], ah[m][1], ah[m][2], ah[m][3], bf.x, bf.y);
                        mma16816(acc[m][j], ah[m][0], ah[m][1], ah[m][2], ah[m][3], bf.z, bf.w);
                        mma16816(acc[m][j], al[m][0], al[m][1], al[m][2], al[m][3], bf.x, bf.y);
                    }
                }
            }
        }
    }
    __syncthreads();

    // ---- epilogue: combine kh halves + bias into SMEM logits ----
    float* L = smem;
    if (kh == 0) {
        #pragma unroll
        for (int m = 0; m < 2; m++) {
            if (m < nMt) {
                #pragma unroll
                for (int j = 0; j < 4; j++) {
                    int c = (nH * 4 + j) * 8 + 2 * q;
                    float b0 = __ldg(&bias[c]);
                    float b1 = __ldg(&bias[c + 1]);
                    int r0 = (ws + 4 * m) * 16 + g;
                    L[r0 * LDL + c]           = acc[m][j][0] + b0;
                    L[r0 * LDL + c + 1]       = acc[m][j][1] + b1;
                    L[(r0 + 8) * LDL + c]     = acc[m][j][2] + b0;
                    L[(r0 + 8) * LDL + c + 1] = acc[m][j][3] + b1;
                }
            }
        }
    }
    __syncthreads();
    if (kh == 1) {
        #pragma unroll
        for (int m = 0; m < 2; m++) {
            if (m < nMt) {
                #pragma unroll
                for (int j = 0; j < 4; j++) {
                    int c = (nH * 4 + j) * 8 + 2 * q;
                    int r0 = (ws + 4 * m) * 16 + g;
                    L[r0 * LDL + c]           += acc[m][j][0];
                    L[r0 * LDL + c + 1]       += acc[m][j][1];
                    L[(r0 + 8) * LDL + c]     += acc[m][j][2];
                    L[(r0 + 8) * LDL + c + 1] += acc[m][j][3];
                }
            }
        }
    }
    __syncthreads();

    // ---- routing: one thread per row ----
    if (t < TMloc) {
        bool any_immature = false;
        #pragma unroll 8
        for (int e = 0; e < N_EXP; e++)
            any_immature |= (__ldg(&mat[e]) == 0);

        float* row = &L[t * LDL];
        if (!any_immature) {
            float v1 = -__int_as_float(0x7f800000), v2 = v1;
            int i1 = 0, i2 = 0;
            #pragma unroll 8
            for (int e = 0; e < N_EXP; e++) {
                float v = row[e];
                if (v > v1)      { v2 = v1; i2 = i1; v1 = v; i1 = e; }
                else if (v > v2) { v2 = v;  i2 = e; }
            }
            float e2  = __expf(v2 - v1);
            float inv = 1.0f / (1.0f + e2);
            #pragma unroll 8
            for (int e = 0; e < N_EXP; e++) row[e] = 0.0f;
            row[i1] = inv;
            row[i2] = e2 * inv;
        } else {
            float m = -__int_as_float(0x7f800000);
            #pragma unroll 8
            for (int e = 0; e < N_EXP; e++) m = fmaxf(m, row[e]);
            float s = 0.0f;
            float tmp[N_EXP];
            #pragma unroll 8
            for (int e = 0; e < N_EXP; e++) {
                float v = __expf((row[e] - m) * (1.0f / TOPK_TEMP));
                tmp[e] = v; s += v;
            }
            float invs = 1.0f / s;
            #pragma unroll 8
            for (int e = 0; e < N_EXP; e++) row[e] = tmp[e] * invs;
        }
    }
    __syncthreads();

    // ---- coalesced float4 store ----
    #pragma unroll
    for (int ss = 0; ss < NCH; ss++) {
        int idx = ss * THREADS + t;
        if (idx < ACH) {
            int r = idx >> 4;
            int c = (idx & 15) << 2;
            float4 v = *(const float4*)&L[r * LDL + c];
            *(float4*)(out + (rowBase + r) * N_EXP + c) = v;
        }
    }
}

__global__ __launch_bounds__(THREADS, 1)
void dhr_mt_kernel(const float* __restrict__ x,
                   const float* __restrict__ bias,
                   const int*   __restrict__ mat,
                   float* __restrict__ out,
                   int aCnt, int mtHi)
{
    extern __shared__ __align__(16) float smem[];
    const int c = blockIdx.x;
    if (mtHi == 7) {
        if (c < aCnt) run_tile<7>((long)c * 112, x, bias, mat, out, smem);
        else          run_tile<6>((long)aCnt * 112 + (long)(c - aCnt) * 96,
                                  x, bias, mat, out, smem);
    } else {
        if (c < aCnt) run_tile<8>((long)c * 128, x, bias, mat, out, smem);
        else          run_tile<7>((long)aCnt * 128 + (long)(c - aCnt) * 112,
                                  x, bias, mat, out, smem);
    }
}

extern "C" void kernel_launch(void* const* d_in, const int* in_sizes, int n_in,
                              void* d_out, int out_size)
{
    const float* x   = (const float*)d_in[0];   // [16384, 2048]
    const float* w   = (const float*)d_in[1];   // [64, 2048]
    const float* b   = (const float*)d_in[2];   // [64]
    const int*   mat = (const int*)  d_in[3];   // [64]
    float* out = (float*)d_out;                 // [16384, 64]

    const int ROWS = in_sizes[0] / K_DIM;       // 16384

    int nsm = 148;
    cudaDeviceGetAttribute(&nsm, cudaDevAttrMultiProcessorCount, 0);

    int grid, aCnt, mtHi, smemB;
    if (nsm * 96 <= ROWS && nsm * 112 >= ROWS) {            // 147..170 SMs
        grid = nsm; mtHi = 7;
        aCnt = (ROWS - 96 * nsm) / 16;                      // CTAs with 112 rows
        smemB = 3 * (112 * ASTRIDE) * 4 + 3 * BWORDS * 4;   // 145920
    } else if (nsm * 112 <= ROWS && nsm * 128 >= ROWS) {    // 128..146 SMs
        grid = nsm; mtHi = 8;
        aCnt = (ROWS - 112 * nsm) / 16;                     // CTAs with 128 rows
        smemB = 3 * (128 * ASTRIDE) * 4 + 3 * BWORDS * 4;   // 159744
    } else {                                                // fallback
        grid = ROWS / 128; mtHi = 8; aCnt = grid;
        smemB = 3 * (128 * ASTRIDE) * 4 + 3 * BWORDS * 4;
    }

    cudaFuncSetAttribute(dhr_mt_kernel,
                         cudaFuncAttributeMaxDynamicSharedMemorySize, smemB);

    dhr_wprep_kernel<<<NKT, 256>>>(w);
    dhr_mt_kernel<<<grid, THREADS, smemB>>>(x, b, mat, out, aCnt, mtHi);
}